// round 14
// baseline (speedup 1.0000x reference)
#include <cuda_runtime.h>
#include <cuda_bf16.h>
#include <cstdint>

#define Bc 2
#define Lc 4096
#define Gc 256
#define HIDc 768
#define Hc 12
#define Dc 64
#define Wc 255
#define BLKc 128
#define Nc 32
#define Vc 32
#define KTOTG (Gc + Lc)   /* 4352 */
#define SCALEc 0.125f
#define GSPLIT 4
#define WSZ (HIDc*HIDc)
#define NLONG (Nc*Hc*Bc)          /* 768 */
#define NGLOB (2*GSPLIT*Bc*Hc)    /* 192 */

// ---------------- device scratch ----------------
__device__ float g_lq[Bc*Lc*HIDc];
__device__ float g_lk[Bc*Lc*HIDc];
__device__ float g_lv[Bc*Lc*HIDc];
__device__ float g_gq[Bc*Gc*HIDc];
__device__ float g_gk[Bc*Gc*HIDc];
__device__ float g_gv[Bc*Gc*HIDc];
__device__ float g_lctx[Bc*Lc*HIDc];
__device__ float g_gctx[Bc*Gc*HIDc];
__device__ float g_lin[Bc*Lc*HIDc];
__device__ float g_gin[Bc*Gc*HIDc];
__device__ float g_wts[4*WSZ];
__device__ float g_gwts[4*WSZ];
__device__ unsigned char g_pl2l[Bc*Lc*Wc];
__device__ unsigned char g_pl2g[Bc*Lc*Gc];
__device__ unsigned char g_pg[Bc*Gc*KTOTG];
__device__ float g_part_acc[(size_t)Bc*Hc*2*GSPLIT*128*64];
__device__ float g_part_l[Bc*Hc*2*GSPLIT*128];

// ---------------- helpers ----------------
__device__ __forceinline__ uint32_t to_tf32(float f) {
    uint32_t r;
    asm("cvt.rna.tf32.f32 %0, %1;" : "=r"(r) : "f"(f));
    return r;
}
__device__ __forceinline__ float round_tf32(float f) {
    return __uint_as_float(to_tf32(f));
}
__device__ __forceinline__ void mma8(float* c, const uint32_t* a, uint32_t b0, uint32_t b1) {
    asm volatile("mma.sync.aligned.m16n8k8.row.col.f32.tf32.tf32.f32 "
        "{%0,%1,%2,%3}, {%4,%5,%6,%7}, {%8,%9}, {%0,%1,%2,%3};"
        : "+f"(c[0]), "+f"(c[1]), "+f"(c[2]), "+f"(c[3])
        : "r"(a[0]), "r"(a[1]), "r"(a[2]), "r"(a[3]), "r"(b0), "r"(b1));
}
__device__ __forceinline__ void cp16(uint32_t dst, const float* src) {
    asm volatile("cp.async.ca.shared.global [%0], [%1], 16;" :: "r"(dst), "l"(src));
}
__device__ __forceinline__ void cp16z(uint32_t dst, const float* src, int nbytes) {
    asm volatile("cp.async.ca.shared.global [%0], [%1], 16, %2;"
                 :: "r"(dst), "l"(src), "r"(nbytes));
}
#define CP_COMMIT() asm volatile("cp.async.commit_group;" ::: "memory")
#define CP_WAIT(n)  asm volatile("cp.async.wait_group %0;" :: "n"(n) : "memory")

// ---------------- fused tf32 pre-conversion ----------------
#define N4A ((Bc*Lc*HIDc)/4)
#define N4G ((Bc*Gc*HIDc)/4)
#define N4W (WSZ/4)
__global__ void cvt_all_kernel(
    const float* __restrict__ s_lin, const float* __restrict__ s_gin,
    const float* __restrict__ w0, const float* __restrict__ w1,
    const float* __restrict__ w2, const float* __restrict__ w3,
    const float* __restrict__ u0, const float* __restrict__ u1,
    const float* __restrict__ u2, const float* __restrict__ u3) {
    int i = blockIdx.x * blockDim.x + threadIdx.x;
    const float* s;
    float* d;
    int off;
    if (i < N4A) { s = s_lin; d = g_lin; off = i; }
    else if (i < N4A + N4G) { s = s_gin; d = g_gin; off = i - N4A; }
    else {
        int j = i - N4A - N4G;
        if (j >= 8*N4W) return;
        int wsel = j / N4W;
        off = j % N4W;
        if (wsel < 4) {
            s = (wsel == 0) ? w0 : (wsel == 1) ? w1 : (wsel == 2) ? w2 : w3;
            d = g_wts + (size_t)wsel * WSZ;
        } else {
            int u = wsel - 4;
            s = (u == 0) ? u0 : (u == 1) ? u1 : (u == 2) ? u2 : u3;
            d = g_gwts + (size_t)u * WSZ;
        }
    }
    float4 v = ((const float4*)s)[off];
    v.x = round_tf32(v.x); v.y = round_tf32(v.y);
    v.z = round_tf32(v.z); v.w = round_tf32(v.w);
    ((float4*)d)[off] = v;
}

// =============== TF32 mma GEMM: cp.async 3-stage ring, 2 CTAs/SM pinned ===============
#define APAD 36
#define BPAD 136
#define ABUFu (128 * APAD)
#define BBUFu (32 * BPAD)
#define STAGEu (ABUFu + BBUFu)
#define GEMM_SMEM (3 * STAGEu * 4)

template<bool ROUND>
__device__ __forceinline__ void gemm_mma_body(
    const float* __restrict__ A, const float* __restrict__ Wm,
    const float* __restrict__ bias, float* __restrict__ C, int m0) {
    extern __shared__ uint32_t smu[];
    const uint32_t sb = (uint32_t)__cvta_generic_to_shared(smu);

    const int tid = threadIdx.x;
    const int warp = tid >> 5, lane = tid & 31;
    const int g = lane >> 2, tg = lane & 3;
    const int wm = (warp >> 2) * 64;
    const int wn = (warp & 3) * 32;
    const int n0 = blockIdx.x * 128;

    float acc[4][4][4];
    #pragma unroll
    for (int mi = 0; mi < 4; ++mi)
        #pragma unroll
        for (int ni = 0; ni < 4; ++ni)
            #pragma unroll
            for (int c = 0; c < 4; ++c) acc[mi][ni][c] = 0.f;

    auto issue = [&](int ch) {
        const int k0 = ch * 32;
        const uint32_t st = sb + (uint32_t)((ch % 3) * STAGEu) * 4u;
        #pragma unroll
        for (int it = 0; it < 4; ++it) {
            int lin = tid + it * 256;
            int row = lin >> 3, f4 = lin & 7;
            cp16(st + (uint32_t)(row * APAD + f4 * 4) * 4u,
                 A + (size_t)(m0 + row) * HIDc + k0 + f4 * 4);
        }
        #pragma unroll
        for (int it = 0; it < 4; ++it) {
            int lin = tid + it * 256;
            int kk = lin >> 5, c4 = lin & 31;
            cp16(st + (uint32_t)(ABUFu + kk * BPAD + c4 * 4) * 4u,
                 Wm + (size_t)(k0 + kk) * HIDc + n0 + c4 * 4);
        }
        CP_COMMIT();
    };

    issue(0);
    issue(1);

    #pragma unroll 1
    for (int ch = 0; ch < 24; ++ch) {
        if (ch < 23) CP_WAIT(1);
        else         CP_WAIT(0);
        __syncthreads();
        const uint32_t* As = smu + (ch % 3) * STAGEu;
        const uint32_t* Bs = As + ABUFu;

        #pragma unroll
        for (int ks = 0; ks < 32; ks += 8) {
            uint32_t af[4][4], bf[4][2];
            #pragma unroll
            for (int mi = 0; mi < 4; ++mi) {
                int mb = wm + mi * 16;
                af[mi][0] = As[(mb + g) * APAD + ks + tg];
                af[mi][1] = As[(mb + g + 8) * APAD + ks + tg];
                af[mi][2] = As[(mb + g) * APAD + ks + tg + 4];
                af[mi][3] = As[(mb + g + 8) * APAD + ks + tg + 4];
            }
            #pragma unroll
            for (int ni = 0; ni < 4; ++ni) {
                int nb = wn + ni * 8 + g;
                bf[ni][0] = Bs[(ks + tg) * BPAD + nb];
                bf[ni][1] = Bs[(ks + tg + 4) * BPAD + nb];
            }
            #pragma unroll
            for (int mi = 0; mi < 4; ++mi)
                #pragma unroll
                for (int ni = 0; ni < 4; ++ni)
                    mma8(acc[mi][ni], af[mi], bf[ni][0], bf[ni][1]);
        }
        if (ch < 22) issue(ch + 2);
    }

    #pragma unroll
    for (int mi = 0; mi < 4; ++mi) {
        #pragma unroll
        for (int ni = 0; ni < 4; ++ni) {
            int r0 = m0 + wm + mi * 16 + g;
            int cc = n0 + wn + ni * 8 + 2 * tg;
            float2 b2 = *(const float2*)(bias + cc);
            float2 v0, v1;
            if (ROUND) {
                v0 = make_float2(round_tf32(acc[mi][ni][0] + b2.x), round_tf32(acc[mi][ni][1] + b2.y));
                v1 = make_float2(round_tf32(acc[mi][ni][2] + b2.x), round_tf32(acc[mi][ni][3] + b2.y));
            } else {
                v0 = make_float2(acc[mi][ni][0] + b2.x, acc[mi][ni][1] + b2.y);
                v1 = make_float2(acc[mi][ni][2] + b2.x, acc[mi][ni][3] + b2.y);
            }
            *(float2*)(C + (size_t)r0 * HIDc + cc) = v0;
            *(float2*)(C + (size_t)(r0 + 8) * HIDc + cc) = v1;
        }
    }
}

__global__ void __launch_bounds__(256, 2) gemm_mma_qkv(
    const float* __restrict__ bq, const float* __restrict__ bk, const float* __restrict__ bv,
    const float* __restrict__ gbq, const float* __restrict__ gbk, const float* __restrict__ gbv) {
    const int z = blockIdx.z;
    if (blockIdx.y < 64) {
        const float* Wm = g_wts + (size_t)z * WSZ;
        const float* bias = (z == 0) ? bq : (z == 1) ? bk : bv;
        float* C = (z == 0) ? g_lq : (z == 1) ? g_lk : g_lv;
        gemm_mma_body<true>(g_lin, Wm, bias, C, blockIdx.y * 128);
    } else {
        const float* Wm = g_gwts + (size_t)z * WSZ;
        const float* bias = (z == 0) ? gbq : (z == 1) ? gbk : gbv;
        float* C = (z == 0) ? g_gq : (z == 1) ? g_gk : g_gv;
        gemm_mma_body<true>(g_gin, Wm, bias, C, (blockIdx.y - 64) * 128);
    }
}

__global__ void __launch_bounds__(256, 2) gemm_mma_out(
    const float* __restrict__ bo_long, const float* __restrict__ bo_glob,
    float* __restrict__ out_long, float* __restrict__ out_glob) {
    if (blockIdx.y < 64)
        gemm_mma_body<false>(g_lctx, g_wts + 3*WSZ, bo_long, out_long, blockIdx.y * 128);
    else
        gemm_mma_body<false>(g_gctx, g_gwts + 3*WSZ, bo_glob, out_glob, (blockIdx.y - 64) * 128);
}

// ---------------- fused mask+id packing ----------------
#define NPL (Bc*Lc*Wc)
#define NPG2 (Bc*Lc*Gc)
#define NPGL (Bc*Gc*KTOTG)
__global__ void pack_all_kernel(
    const int* __restrict__ l2l_m, const int* __restrict__ l2l_i,
    const int* __restrict__ l2g_m, const int* __restrict__ l2g_i,
    const int* __restrict__ gg_m, const int* __restrict__ gg_i,
    const int* __restrict__ gl_m, const int* __restrict__ gl_i) {
    int i = blockIdx.x * blockDim.x + threadIdx.x;
    if (i < NPL) {
        g_pl2l[i] = (unsigned char)((l2l_i[i] & 31) | (l2l_m[i] ? 0x80 : 0));
        return;
    }
    i -= NPL;
    if (i < NPG2) {
        g_pl2g[i] = (unsigned char)((l2g_i[i] & 31) | (l2g_m[i] ? 0x80 : 0));
        return;
    }
    i -= NPG2;
    if (i >= NPGL) return;
    int row = i / KTOTG, col = i % KTOTG;
    unsigned char v;
    if (col < Gc) { int idx = row*Gc + col;        v = (unsigned char)((gg_i[idx] & 31) | (gg_m[idx] ? 0x80 : 0)); }
    else          { int idx = row*Lc + (col - Gc); v = (unsigned char)((gl_i[idx] & 31) | (gl_m[idx] ? 0x80 : 0)); }
    g_pg[i] = v;
}

// =============== fused mma attention: cp.async pipelined, glob-first ===============
// smem: sQ/sP 34816 @0 | sRel 16896 @34816 (rel_emb staged here first) |
//       sK0 17408 @51712 | sK1 17408 @69120 | sV 18432 @86528 ; total 104960
#define OFF_REL 34816
#define OFF_K0  51712
#define KBUF    17408
#define OFF_V   86528
#define ATT_SMEM 104960

__global__ void __launch_bounds__(256, 2) attn_mma(
    const float* __restrict__ rel_embL, const float* __restrict__ rel_biasL,
    const float* __restrict__ rel_embG, const float* __restrict__ rel_biasG) {
    extern __shared__ char sm[];
    uint32_t* sQ   = (uint32_t*)sm;
    float*    sRel = (float*)(sm + OFF_REL);
    uint32_t* sRelU = (uint32_t*)(sm + OFF_REL);
    const uint32_t sb = (uint32_t)__cvta_generic_to_shared(sm);

    const int tid = threadIdx.x;
    const int warp = tid >> 5, lane = tid & 31;
    const int g = lane >> 2, tg = lane & 3;
    const int pr0 = warp * 16 + g, pr1 = pr0 + 8;
    const int bid = blockIdx.x;
    const bool isGlob = (bid < NGLOB);

    // ---- common decode ----
    int b, h, NT;
    int t0 = 0, jbase = 0;      // long
    int q0 = 0, split = 0;      // glob
    int qt = 0, bh = 0;
    if (isGlob) {
        const int gid = bid;
        qt = gid & 1;
        split = (gid >> 1) & (GSPLIT - 1);
        bh = gid >> 3;
        b = bh / Hc; h = bh % Hc;
        q0 = qt * 128;
        NT = 17;
    } else {
        const int lid = bid - NGLOB;
        const int n = lid & 31;
        h = (lid >> 5) % Hc;
        b = lid / (Nc * Hc);
        t0 = n * BLKc;
        jbase = (n - 1) * BLKc;
        NT = 10;
    }

    // ---- K/V tile prefetch helpers (cp.async) ----
    auto issueK = [&](int t) {
        const uint32_t kb = sb + OFF_K0 + (uint32_t)(t & 1) * KBUF;
        #pragma unroll
        for (int it = 0; it < 4; ++it) {
            int lin = tid + it * 256;
            int kk = lin >> 4, f4 = lin & 15;
            const float* src;
            int sz = 16;
            if (isGlob) {
                int j = (split * 17 + t) * 64 + kk;
                if (j < Gc) src = g_gk + (((size_t)b*Gc + j)*Hc + h)*Dc + f4*4;
                else        src = g_lk + (((size_t)b*Lc + (j - Gc))*Hc + h)*Dc + f4*4;
            } else if (t < 6) {
                int j = jbase + t*64 + kk;
                bool ok = (j >= 0) && (j < Lc);
                src = g_lk + (((size_t)b*Lc + (ok ? j : 0))*Hc + h)*Dc + f4*4;
                sz = ok ? 16 : 0;
            } else {
                int j = (t - 6)*64 + kk;
                src = g_gk + (((size_t)b*Gc + j)*Hc + h)*Dc + f4*4;
            }
            cp16z(kb + (uint32_t)(kk*68 + f4*4)*4u, src, sz);
        }
        CP_COMMIT();
    };
    auto issueV = [&](int t) {
        const uint32_t vb = sb + OFF_V;
        #pragma unroll
        for (int it = 0; it < 4; ++it) {
            int lin = tid + it * 256;
            int kk = lin >> 4, f4 = lin & 15;
            const float* src;
            int sz = 16;
            if (isGlob) {
                int j = (split * 17 + t) * 64 + kk;
                if (j < Gc) src = g_gv + (((size_t)b*Gc + j)*Hc + h)*Dc + f4*4;
                else        src = g_lv + (((size_t)b*Lc + (j - Gc))*Hc + h)*Dc + f4*4;
            } else if (t < 6) {
                int j = jbase + t*64 + kk;
                bool ok = (j >= 0) && (j < Lc);
                src = g_lv + (((size_t)b*Lc + (ok ? j : 0))*Hc + h)*Dc + f4*4;
                sz = ok ? 16 : 0;
            } else {
                int j = (t - 6)*64 + kk;
                src = g_gv + (((size_t)b*Gc + j)*Hc + h)*Dc + f4*4;
            }
            cp16z(vb + (uint32_t)(kk*72 + f4*4)*4u, src, sz);
        }
        CP_COMMIT();
    };

    // prefetch K0, V0, K1 (overlaps Q/rel prologue)
    issueK(0);
    issueV(0);
    issueK(1);

    // ---- Q staging ----
    const float* Qsrc = isGlob ? (g_gq + (((size_t)b*Gc + q0)*Hc + h)*Dc)
                               : (g_lq + (((size_t)b*Lc + t0)*Hc + h)*Dc);
    #pragma unroll
    for (int it = 0; it < 8; ++it) {
        int lin = tid + it * 256;
        int row = lin >> 4, f4 = lin & 15;
        uint4 v = *(const uint4*)(Qsrc + (size_t)row*Hc*Dc + f4*4);
        *(uint4*)&sQ[row * 68 + f4 * 4] = v;
    }
    // rel_emb staged into sRel area (32 rows x 64, stride 68)
    const float* relE = isGlob ? rel_embG : rel_embL;
    const float* relB = isGlob ? rel_biasG : rel_biasL;
    #pragma unroll
    for (int it = 0; it < 2; ++it) {
        int lin = tid + it * 256;
        int r = lin >> 4, f4 = lin & 15;
        float4 v = *(const float4*)(relE + ((size_t)r*Hc + h)*Dc + f4*4);
        uint4 w;
        w.x = to_tf32(v.x); w.y = to_tf32(v.y); w.z = to_tf32(v.z); w.w = to_tf32(v.w);
        *(uint4*)&sRelU[r * 68 + f4 * 4] = w;
    }
    __syncthreads();

    uint32_t qa[8][4];
    #pragma unroll
    for (int kf = 0; kf < 8; ++kf) {
        int k0 = kf * 8;
        qa[kf][0] = sQ[pr0 * 68 + k0 + tg];
        qa[kf][1] = sQ[pr1 * 68 + k0 + tg];
        qa[kf][2] = sQ[pr0 * 68 + k0 + tg + 4];
        qa[kf][3] = sQ[pr1 * 68 + k0 + tg + 4];
    }

    float rc[4][4];
    #pragma unroll
    for (int nf = 0; nf < 4; ++nf)
        #pragma unroll
        for (int e = 0; e < 4; ++e) rc[nf][e] = 0.f;
    #pragma unroll
    for (int kf = 0; kf < 8; ++kf)
        #pragma unroll
        for (int nf = 0; nf < 4; ++nf) {
            uint32_t b0 = sRelU[(nf*8 + g) * 68 + kf*8 + tg];
            uint32_t b1 = sRelU[(nf*8 + g) * 68 + kf*8 + tg + 4];
            mma8(rc[nf], qa[kf], b0, b1);
        }
    __syncthreads();   // all warps done reading staged rel before score writes
    #pragma unroll
    for (int nf = 0; nf < 4; ++nf) {
        int c = nf * 8 + 2 * tg;
        sRel[pr0*33 + c]     = rc[nf][0] + relB[c*Hc + h];
        sRel[pr0*33 + c + 1] = rc[nf][1] + relB[(c+1)*Hc + h];
        sRel[pr1*33 + c]     = rc[nf][2] + relB[c*Hc + h];
        sRel[pr1*33 + c + 1] = rc[nf][3] + relB[(c+1)*Hc + h];
    }

    float accO[8][4];
    #pragma unroll
    for (int nf = 0; nf < 8; ++nf)
        #pragma unroll
        for (int e = 0; e < 4; ++e) accO[nf][e] = 0.f;
    float ls0 = 0.f, ls1 = 0.f;

    // mask/id row pointers
    const unsigned char *prow0A, *prow1A, *prow0B = 0, *prow1B = 0;
    if (isGlob) {
        prow0A = g_pg + (size_t)(b*Gc + q0 + pr0)*KTOTG;
        prow1A = g_pg + (size_t)(b*Gc + q0 + pr1)*KTOTG;
    } else {
        prow0A = g_pl2l + (size_t)(b*Lc + t0 + pr0)*Wc;
        prow1A = g_pl2l + (size_t)(b*Lc + t0 + pr1)*Wc;
        prow0B = g_pl2g + (size_t)(b*Lc + t0 + pr0)*Gc;
        prow1B = g_pl2g + (size_t)(b*Lc + t0 + pr1)*Gc;
    }

    #pragma unroll 1
    for (int t = 0; t < NT; ++t) {
        if (t == NT - 1) CP_WAIT(0);
        else             CP_WAIT(1);
        __syncthreads();
        const uint32_t* sK = (const uint32_t*)(sm + OFF_K0 + (t & 1) * KBUF);
        const uint32_t* sV = (const uint32_t*)(sm + OFF_V);

        // S = Q @ K^T
        float sc[8][4];
        #pragma unroll
        for (int nf = 0; nf < 8; ++nf)
            #pragma unroll
            for (int e = 0; e < 4; ++e) sc[nf][e] = 0.f;
        #pragma unroll
        for (int kf = 0; kf < 8; ++kf)
            #pragma unroll
            for (int nf = 0; nf < 8; ++nf) {
                uint32_t b0 = sK[(nf*8 + g) * 68 + kf*8 + tg];
                uint32_t b1 = sK[(nf*8 + g) * 68 + kf*8 + tg + 4];
                mma8(sc[nf], qa[kf], b0, b1);
            }

        // softmax numerators + P staging
        #pragma unroll
        for (int nf = 0; nf < 8; ++nf) {
            uint2 pw;
            #pragma unroll
            for (int half = 0; half < 2; ++half) {
                const int pr = half ? pr1 : pr0;
                float ps = 0.f;
                #pragma unroll
                for (int sub = 0; sub < 2; ++sub) {
                    const int e = half*2 + sub;
                    const int cl = nf*8 + 2*tg + sub;
                    unsigned char byt; bool ok;
                    if (isGlob) {
                        byt = (half ? prow1A : prow0A)[(split*17 + t)*64 + cl];
                        ok = true;
                    } else if (t < 6) {
                        int c = t*64 + cl;
                        int r = c - pr - 1;
                        int j = jbase + c;
                        ok = (r >= 0) && (r < Wc) && (j >= 0) && (j < Lc);
                        byt = ok ? (half ? prow1A : prow0A)[r] : (unsigned char)0;
                    } else {
                        byt = (half ? prow1B : prow0B)[(t - 6)*64 + cl];
                        ok = true;
                    }
                    ok = ok && (byt & 0x80);
                    float s = (sc[nf][e] + sRel[pr*33 + (byt & 31)]) * SCALEc;
                    float p = ok ? __expf(s) : 0.f;
                    uint32_t pt = to_tf32(p);
                    ps += __uint_as_float(pt);
                    if (sub == 0) pw.x = pt; else pw.y = pt;
                }
                if (half == 0) ls0 += ps; else ls1 += ps;
                *(uint2*)&sQ[pr*68 + nf*8 + 2*tg] = pw;
            }
        }
        __syncwarp();

        // O += P @ V
        #pragma unroll
        for (int kf = 0; kf < 8; ++kf) {
            uint32_t pa[4];
            pa[0] = sQ[pr0*68 + kf*8 + tg];
            pa[1] = sQ[pr1*68 + kf*8 + tg];
            pa[2] = sQ[pr0*68 + kf*8 + tg + 4];
            pa[3] = sQ[pr1*68 + kf*8 + tg + 4];
            #pragma unroll
            for (int nf = 0; nf < 8; ++nf) {
                uint32_t b0 = sV[(kf*8 + tg) * 72 + nf*8 + g];
                uint32_t b1 = sV[(kf*8 + tg + 4) * 72 + nf*8 + g];
                mma8(accO[nf], pa, b0, b1);
            }
        }
        __syncthreads();   // all warps done with V(t) and K(t)
        if (t + 1 < NT) issueV(t + 1);
        if (t + 2 < NT) issueK(t + 2);
    }

    ls0 += __shfl_xor_sync(0xFFFFFFFF, ls0, 1);
    ls0 += __shfl_xor_sync(0xFFFFFFFF, ls0, 2);
    ls1 += __shfl_xor_sync(0xFFFFFFFF, ls1, 1);
    ls1 += __shfl_xor_sync(0xFFFFFFFF, ls1, 2);

    if (isGlob) {
        const int pi = (bh * 2 + qt) * GSPLIT + split;
        float* pa = g_part_acc + (size_t)pi * 128 * 64;
        #pragma unroll
        for (int nf = 0; nf < 8; ++nf) {
            int c = nf*8 + 2*tg;
            *(float2*)(pa + pr0*64 + c) = make_float2(accO[nf][0], accO[nf][1]);
            *(float2*)(pa + pr1*64 + c) = make_float2(accO[nf][2], accO[nf][3]);
        }
        if (tg == 0) {
            g_part_l[pi*128 + pr0] = ls0;
            g_part_l[pi*128 + pr1] = ls1;
        }
    } else {
        const float inv0 = 1.f / ls0, inv1 = 1.f / ls1;
        #pragma unroll
        for (int nf = 0; nf < 8; ++nf) {
            int c = nf*8 + 2*tg;
            float2 v0 = make_float2(round_tf32(accO[nf][0]*inv0), round_tf32(accO[nf][1]*inv0));
            float2 v1 = make_float2(round_tf32(accO[nf][2]*inv1), round_tf32(accO[nf][3]*inv1));
            *(float2*)(g_lctx + (((size_t)b*Lc + t0 + pr0)*Hc + h)*Dc + c) = v0;
            *(float2*)(g_lctx + (((size_t)b*Lc + t0 + pr1)*Hc + h)*Dc + c) = v1;
        }
    }
}

__global__ void glob_combine2() {
    const int bq = blockIdx.x >> 7;
    const int row = blockIdx.x & 127;
    const int d = threadIdx.x;
    const int bh = bq >> 1, qt = bq & 1;
    const int b = bh / Hc, h = bh % Hc;
    const int qi = qt * 128 + row;
    float a = 0.f, l = 0.f;
    #pragma unroll
    for (int s = 0; s < GSPLIT; ++s) {
        int pi = bq * GSPLIT + s;
        a += g_part_acc[(size_t)pi*128*64 + row*64 + d];
        l += g_part_l[pi*128 + row];
    }
    g_gctx[(((size_t)b*Gc + qi)*Hc + h)*Dc + d] = round_tf32(a / l);
}

// ---------------- host launcher ----------------
extern "C" void kernel_launch(void* const* d_in, const int* in_sizes, int n_in,
                              void* d_out, int out_size) {
    (void)in_sizes; (void)n_in; (void)out_size;

    const float* long_input   = (const float*)d_in[0];
    const float* global_input = (const float*)d_in[1];
    const int* l2l_m = (const int*)d_in[2];
    const int* g2g_m = (const int*)d_in[3];
    const int* l2g_m = (const int*)d_in[4];
    const int* g2l_m = (const int*)d_in[5];
    const int* l2l_i = (const int*)d_in[6];
    const int* g2g_i = (const int*)d_in[7];
    const int* l2g_i = (const int*)d_in[8];
    const int* g2l_i = (const int*)d_in[9];
    const float* wq_long = (const float*)d_in[10];
    const float* bq_long = (const float*)d_in[11];
    const float* wk_long = (const float*)d_in[12];
    const float* bk_long = (const float*)d_in[13];
    const float* wv_long = (const float*)d_in[14];
    const float* bv_long = (const float*)d_in[15];
    const float* wq_glob = (const float*)d_in[16];
    const float* bq_glob = (const float*)d_in[17];
    const float* wk_glob = (const float*)d_in[18];
    const float* bk_glob = (const float*)d_in[19];
    const float* wv_glob = (const float*)d_in[20];
    const float* bv_glob = (const float*)d_in[21];
    const float* rel_emb_long  = (const float*)d_in[22];
    const float* rel_bias_long = (const float*)d_in[23];
    const float* rel_emb_glob  = (const float*)d_in[24];
    const float* rel_bias_glob = (const float*)d_in[25];
    const float* wo_long = (const float*)d_in[26];
    const float* bo_long = (const float*)d_in[27];
    const float* wo_glob = (const float*)d_in[28];
    const float* bo_glob = (const float*)d_in[29];

    cudaFuncSetAttribute(gemm_mma_qkv, cudaFuncAttributeMaxDynamicSharedMemorySize, GEMM_SMEM);
    cudaFuncSetAttribute(gemm_mma_out, cudaFuncAttributeMaxDynamicSharedMemorySize, GEMM_SMEM);
    cudaFuncSetAttribute(attn_mma, cudaFuncAttributeMaxDynamicSharedMemorySize, ATT_SMEM);

    // 0) pre-convert inputs/weights
    {
        int n4 = N4A + N4G + 8*N4W;
        cvt_all_kernel<<<(n4 + 255)/256, 256>>>(long_input, global_input,
                                                wq_long, wk_long, wv_long, wo_long,
                                                wq_glob, wk_glob, wv_glob, wo_glob);
    }

    // 1) pack mask+id bytes
    {
        int ntot = NPL + NPG2 + NPGL;
        pack_all_kernel<<<(ntot + 255)/256, 256>>>(l2l_m, l2l_i, l2g_m, l2g_i,
                                                   g2g_m, g2g_i, g2l_m, g2l_i);
    }

    // 2) all QKV projections in one launch
    dim3 gqkv(HIDc/128, 68, 3);
    gemm_mma_qkv<<<gqkv, 256, GEMM_SMEM>>>(bq_long, bk_long, bv_long,
                                           bq_glob, bk_glob, bv_glob);

    // 3) fused attention (glob CTAs first)
    attn_mma<<<NLONG + NGLOB, 256, ATT_SMEM>>>(rel_emb_long, rel_bias_long,
                                               rel_emb_glob, rel_bias_glob);
    glob_combine2<<<Bc*Hc*2*128, 64>>>();

    // 4) both output projections in one launch
    float* out_long = (float*)d_out;
    float* out_glob = out_long + (size_t)Bc*Lc*HIDc;
    dim3 gout(HIDc/128, 68);
    gemm_mma_out<<<gout, 256, GEMM_SMEM>>>(bo_long, bo_glob, out_long, out_glob);
}

// round 15
// speedup vs baseline: 1.1479x; 1.1479x over previous
#include <cuda_runtime.h>
#include <cuda_bf16.h>
#include <cstdint>

#define Bc 2
#define Lc 4096
#define Gc 256
#define HIDc 768
#define Hc 12
#define Dc 64
#define Wc 255
#define BLKc 128
#define Nc 32
#define Vc 32
#define KTOTG (Gc + Lc)   /* 4352 */
#define SCALEc 0.125f
#define GSPLIT 4
#define WSZ (HIDc*HIDc)
#define NLONG (Nc*Hc*Bc)          /* 768 */
#define NGLOB (2*GSPLIT*Bc*Hc)    /* 192 */

// ---------------- device scratch ----------------
__device__ float g_lq[Bc*Lc*HIDc];
__device__ float g_lk[Bc*Lc*HIDc];
__device__ float g_lv[Bc*Lc*HIDc];
__device__ float g_gq[Bc*Gc*HIDc];
__device__ float g_gk[Bc*Gc*HIDc];
__device__ float g_gv[Bc*Gc*HIDc];
__device__ float g_lctx[Bc*Lc*HIDc];
__device__ float g_gctx[Bc*Gc*HIDc];
__device__ float g_lin[Bc*Lc*HIDc];
__device__ float g_gin[Bc*Gc*HIDc];
__device__ float g_wts[4*WSZ];
__device__ float g_gwts[4*WSZ];
__device__ unsigned char g_pl2l[Bc*Lc*Wc];
__device__ unsigned char g_pl2g[Bc*Lc*Gc];
__device__ unsigned char g_pg[Bc*Gc*KTOTG];
__device__ float g_part_acc[(size_t)Bc*Hc*2*GSPLIT*128*64];
__device__ float g_part_l[Bc*Hc*2*GSPLIT*128];

// ---------------- helpers ----------------
__device__ __forceinline__ uint32_t to_tf32(float f) {
    uint32_t r;
    asm("cvt.rna.tf32.f32 %0, %1;" : "=r"(r) : "f"(f));
    return r;
}
__device__ __forceinline__ float round_tf32(float f) {
    return __uint_as_float(to_tf32(f));
}
__device__ __forceinline__ void mma8(float* c, const uint32_t* a, uint32_t b0, uint32_t b1) {
    asm volatile("mma.sync.aligned.m16n8k8.row.col.f32.tf32.tf32.f32 "
        "{%0,%1,%2,%3}, {%4,%5,%6,%7}, {%8,%9}, {%0,%1,%2,%3};"
        : "+f"(c[0]), "+f"(c[1]), "+f"(c[2]), "+f"(c[3])
        : "r"(a[0]), "r"(a[1]), "r"(a[2]), "r"(a[3]), "r"(b0), "r"(b1));
}
__device__ __forceinline__ void cp16(uint32_t dst, const float* src) {
    asm volatile("cp.async.ca.shared.global [%0], [%1], 16;" :: "r"(dst), "l"(src));
}

// ---------------- fused tf32 pre-conversion ----------------
#define N4A ((Bc*Lc*HIDc)/4)
#define N4G ((Bc*Gc*HIDc)/4)
#define N4W (WSZ/4)
__global__ void cvt_all_kernel(
    const float* __restrict__ s_lin, const float* __restrict__ s_gin,
    const float* __restrict__ w0, const float* __restrict__ w1,
    const float* __restrict__ w2, const float* __restrict__ w3,
    const float* __restrict__ u0, const float* __restrict__ u1,
    const float* __restrict__ u2, const float* __restrict__ u3) {
    int i = blockIdx.x * blockDim.x + threadIdx.x;
    const float* s;
    float* d;
    int off;
    if (i < N4A) { s = s_lin; d = g_lin; off = i; }
    else if (i < N4A + N4G) { s = s_gin; d = g_gin; off = i - N4A; }
    else {
        int j = i - N4A - N4G;
        if (j >= 8*N4W) return;
        int wsel = j / N4W;
        off = j % N4W;
        if (wsel < 4) {
            s = (wsel == 0) ? w0 : (wsel == 1) ? w1 : (wsel == 2) ? w2 : w3;
            d = g_wts + (size_t)wsel * WSZ;
        } else {
            int u = wsel - 4;
            s = (u == 0) ? u0 : (u == 1) ? u1 : (u == 2) ? u2 : u3;
            d = g_gwts + (size_t)u * WSZ;
        }
    }
    float4 v = ((const float4*)s)[off];
    v.x = round_tf32(v.x); v.y = round_tf32(v.y);
    v.z = round_tf32(v.z); v.w = round_tf32(v.w);
    ((float4*)d)[off] = v;
}

// =============== TF32 mma GEMM: cp.async 3-stage ring, 2 CTAs/SM pinned ===============
#define APAD 36
#define BPAD 136
#define ABUFu (128 * APAD)
#define BBUFu (32 * BPAD)
#define STAGEu (ABUFu + BBUFu)
#define GEMM_SMEM (3 * STAGEu * 4)

template<bool ROUND>
__device__ __forceinline__ void gemm_mma_body(
    const float* __restrict__ A, const float* __restrict__ Wm,
    const float* __restrict__ bias, float* __restrict__ C, int m0) {
    extern __shared__ uint32_t smu[];
    const uint32_t sb = (uint32_t)__cvta_generic_to_shared(smu);

    const int tid = threadIdx.x;
    const int warp = tid >> 5, lane = tid & 31;
    const int g = lane >> 2, tg = lane & 3;
    const int wm = (warp >> 2) * 64;
    const int wn = (warp & 3) * 32;
    const int n0 = blockIdx.x * 128;

    float acc[4][4][4];
    #pragma unroll
    for (int mi = 0; mi < 4; ++mi)
        #pragma unroll
        for (int ni = 0; ni < 4; ++ni)
            #pragma unroll
            for (int c = 0; c < 4; ++c) acc[mi][ni][c] = 0.f;

    auto issue = [&](int ch) {
        const int k0 = ch * 32;
        const uint32_t st = sb + (uint32_t)((ch % 3) * STAGEu) * 4u;
        #pragma unroll
        for (int it = 0; it < 4; ++it) {
            int lin = tid + it * 256;
            int row = lin >> 3, f4 = lin & 7;
            cp16(st + (uint32_t)(row * APAD + f4 * 4) * 4u,
                 A + (size_t)(m0 + row) * HIDc + k0 + f4 * 4);
        }
        #pragma unroll
        for (int it = 0; it < 4; ++it) {
            int lin = tid + it * 256;
            int kk = lin >> 5, c4 = lin & 31;
            cp16(st + (uint32_t)(ABUFu + kk * BPAD + c4 * 4) * 4u,
                 Wm + (size_t)(k0 + kk) * HIDc + n0 + c4 * 4);
        }
        asm volatile("cp.async.commit_group;" ::: "memory");
    };

    issue(0);
    issue(1);

    #pragma unroll 1
    for (int ch = 0; ch < 24; ++ch) {
        if (ch < 23) asm volatile("cp.async.wait_group 1;" ::: "memory");
        else         asm volatile("cp.async.wait_group 0;" ::: "memory");
        __syncthreads();
        const uint32_t* As = smu + (ch % 3) * STAGEu;
        const uint32_t* Bs = As + ABUFu;

        #pragma unroll
        for (int ks = 0; ks < 32; ks += 8) {
            uint32_t af[4][4], bf[4][2];
            #pragma unroll
            for (int mi = 0; mi < 4; ++mi) {
                int mb = wm + mi * 16;
                af[mi][0] = As[(mb + g) * APAD + ks + tg];
                af[mi][1] = As[(mb + g + 8) * APAD + ks + tg];
                af[mi][2] = As[(mb + g) * APAD + ks + tg + 4];
                af[mi][3] = As[(mb + g + 8) * APAD + ks + tg + 4];
            }
            #pragma unroll
            for (int ni = 0; ni < 4; ++ni) {
                int nb = wn + ni * 8 + g;
                bf[ni][0] = Bs[(ks + tg) * BPAD + nb];
                bf[ni][1] = Bs[(ks + tg + 4) * BPAD + nb];
            }
            #pragma unroll
            for (int mi = 0; mi < 4; ++mi)
                #pragma unroll
                for (int ni = 0; ni < 4; ++ni)
                    mma8(acc[mi][ni], af[mi], bf[ni][0], bf[ni][1]);
        }
        if (ch < 22) issue(ch + 2);
    }

    #pragma unroll
    for (int mi = 0; mi < 4; ++mi) {
        #pragma unroll
        for (int ni = 0; ni < 4; ++ni) {
            int r0 = m0 + wm + mi * 16 + g;
            int cc = n0 + wn + ni * 8 + 2 * tg;
            float2 b2 = *(const float2*)(bias + cc);
            float2 v0, v1;
            if (ROUND) {
                v0 = make_float2(round_tf32(acc[mi][ni][0] + b2.x), round_tf32(acc[mi][ni][1] + b2.y));
                v1 = make_float2(round_tf32(acc[mi][ni][2] + b2.x), round_tf32(acc[mi][ni][3] + b2.y));
            } else {
                v0 = make_float2(acc[mi][ni][0] + b2.x, acc[mi][ni][1] + b2.y);
                v1 = make_float2(acc[mi][ni][2] + b2.x, acc[mi][ni][3] + b2.y);
            }
            *(float2*)(C + (size_t)r0 * HIDc + cc) = v0;
            *(float2*)(C + (size_t)(r0 + 8) * HIDc + cc) = v1;
        }
    }
}

__global__ void __launch_bounds__(256, 2) gemm_mma_qkv(
    const float* __restrict__ bq, const float* __restrict__ bk, const float* __restrict__ bv,
    const float* __restrict__ gbq, const float* __restrict__ gbk, const float* __restrict__ gbv) {
    const int z = blockIdx.z;
    if (blockIdx.y < 64) {
        const float* Wm = g_wts + (size_t)z * WSZ;
        const float* bias = (z == 0) ? bq : (z == 1) ? bk : bv;
        float* C = (z == 0) ? g_lq : (z == 1) ? g_lk : g_lv;
        gemm_mma_body<true>(g_lin, Wm, bias, C, blockIdx.y * 128);
    } else {
        const float* Wm = g_gwts + (size_t)z * WSZ;
        const float* bias = (z == 0) ? gbq : (z == 1) ? gbk : gbv;
        float* C = (z == 0) ? g_gq : (z == 1) ? g_gk : g_gv;
        gemm_mma_body<true>(g_gin, Wm, bias, C, (blockIdx.y - 64) * 128);
    }
}

__global__ void __launch_bounds__(256, 2) gemm_mma_out(
    const float* __restrict__ bo_long, const float* __restrict__ bo_glob,
    float* __restrict__ out_long, float* __restrict__ out_glob) {
    if (blockIdx.y < 64)
        gemm_mma_body<false>(g_lctx, g_wts + 3*WSZ, bo_long, out_long, blockIdx.y * 128);
    else
        gemm_mma_body<false>(g_gctx, g_gwts + 3*WSZ, bo_glob, out_glob, (blockIdx.y - 64) * 128);
}

// ---------------- fused mask+id packing ----------------
#define NPL (Bc*Lc*Wc)
#define NPG2 (Bc*Lc*Gc)
#define NPGL (Bc*Gc*KTOTG)
__global__ void pack_all_kernel(
    const int* __restrict__ l2l_m, const int* __restrict__ l2l_i,
    const int* __restrict__ l2g_m, const int* __restrict__ l2g_i,
    const int* __restrict__ gg_m, const int* __restrict__ gg_i,
    const int* __restrict__ gl_m, const int* __restrict__ gl_i) {
    int i = blockIdx.x * blockDim.x + threadIdx.x;
    if (i < NPL) {
        g_pl2l[i] = (unsigned char)((l2l_i[i] & 31) | (l2l_m[i] ? 0x80 : 0));
        return;
    }
    i -= NPL;
    if (i < NPG2) {
        g_pl2g[i] = (unsigned char)((l2g_i[i] & 31) | (l2g_m[i] ? 0x80 : 0));
        return;
    }
    i -= NPG2;
    if (i >= NPGL) return;
    int row = i / KTOTG, col = i % KTOTG;
    unsigned char v;
    if (col < Gc) { int idx = row*Gc + col;        v = (unsigned char)((gg_i[idx] & 31) | (gg_m[idx] ? 0x80 : 0)); }
    else          { int idx = row*Lc + (col - Gc); v = (unsigned char)((gl_i[idx] & 31) | (gl_m[idx] ? 0x80 : 0)); }
    g_pg[i] = v;
}

// =============== fused mma attention: long + glob in ONE launch (glob-first) ===============
#define ATT_SMEM 87552
#define OFF_K 34816
#define OFF_V 52224
#define OFF_REL 70656

__global__ void __launch_bounds__(256, 2) attn_mma(
    const float* __restrict__ rel_embL, const float* __restrict__ rel_biasL,
    const float* __restrict__ rel_embG, const float* __restrict__ rel_biasG) {
    extern __shared__ char sm[];
    uint32_t* sQ  = (uint32_t*)sm;              // reused as sP
    uint32_t* sK  = (uint32_t*)(sm + OFF_K);
    uint32_t* sV  = (uint32_t*)(sm + OFF_V);
    float*    sRel = (float*)(sm + OFF_REL);

    const int tid = threadIdx.x;
    const int warp = tid >> 5, lane = tid & 31;
    const int g = lane >> 2, tg = lane & 3;
    const int pr0 = warp * 16 + g, pr1 = pr0 + 8;
    const int bid = blockIdx.x;

    if (bid >= NGLOB) {
        // ================= long-token attention =================
        const int lid = bid - NGLOB;
        const int n = lid & 31, h = (lid >> 5) % Hc, b = lid / (Nc * Hc);
        const int t0 = n * BLKc;
        const int jbase = (n - 1) * BLKc;

        #pragma unroll
        for (int it = 0; it < 8; ++it) {
            int lin = tid + it * 256;
            int row = lin >> 4, f4 = lin & 15;
            uint4 v = *(const uint4*)(g_lq + (((size_t)b*Lc + t0 + row)*Hc + h)*Dc + f4*4);
            *(uint4*)&sQ[row * 68 + f4 * 4] = v;
        }
        #pragma unroll
        for (int it = 0; it < 2; ++it) {
            int lin = tid + it * 256;
            int r = lin >> 4, f4 = lin & 15;
            float4 v = *(const float4*)(rel_embL + ((size_t)r*Hc + h)*Dc + f4*4);
            uint4 w;
            w.x = to_tf32(v.x); w.y = to_tf32(v.y); w.z = to_tf32(v.z); w.w = to_tf32(v.w);
            *(uint4*)&sK[r * 68 + f4 * 4] = w;
        }
        __syncthreads();

        uint32_t qa[8][4];
        #pragma unroll
        for (int kf = 0; kf < 8; ++kf) {
            int k0 = kf * 8;
            qa[kf][0] = sQ[pr0 * 68 + k0 + tg];
            qa[kf][1] = sQ[pr1 * 68 + k0 + tg];
            qa[kf][2] = sQ[pr0 * 68 + k0 + tg + 4];
            qa[kf][3] = sQ[pr1 * 68 + k0 + tg + 4];
        }

        {
            float rc[4][4];
            #pragma unroll
            for (int nf = 0; nf < 4; ++nf)
                #pragma unroll
                for (int e = 0; e < 4; ++e) rc[nf][e] = 0.f;
            #pragma unroll
            for (int kf = 0; kf < 8; ++kf)
                #pragma unroll
                for (int nf = 0; nf < 4; ++nf) {
                    uint32_t b0 = sK[(nf*8 + g) * 68 + kf*8 + tg];
                    uint32_t b1 = sK[(nf*8 + g) * 68 + kf*8 + tg + 4];
                    mma8(rc[nf], qa[kf], b0, b1);
                }
            #pragma unroll
            for (int nf = 0; nf < 4; ++nf) {
                int c = nf * 8 + 2 * tg;
                sRel[pr0*33 + c]     = rc[nf][0] + rel_biasL[c*Hc + h];
                sRel[pr0*33 + c + 1] = rc[nf][1] + rel_biasL[(c+1)*Hc + h];
                sRel[pr1*33 + c]     = rc[nf][2] + rel_biasL[c*Hc + h];
                sRel[pr1*33 + c + 1] = rc[nf][3] + rel_biasL[(c+1)*Hc + h];
            }
        }

        float accO[8][4];
        #pragma unroll
        for (int nf = 0; nf < 8; ++nf)
            #pragma unroll
            for (int e = 0; e < 4; ++e) accO[nf][e] = 0.f;
        float ls0 = 0.f, ls1 = 0.f;

        const unsigned char* prow0L = g_pl2l + (size_t)(b*Lc + t0 + pr0)*Wc;
        const unsigned char* prow1L = g_pl2l + (size_t)(b*Lc + t0 + pr1)*Wc;
        const unsigned char* prow0G = g_pl2g + (size_t)(b*Lc + t0 + pr0)*Gc;
        const unsigned char* prow1G = g_pl2g + (size_t)(b*Lc + t0 + pr1)*Gc;

        #pragma unroll 1
        for (int tile = 0; tile < 10; ++tile) {
            __syncthreads();
            if (tile < 6) {
                const int c0 = tile * 64;
                #pragma unroll
                for (int it = 0; it < 4; ++it) {
                    int lin = tid + it * 256;
                    int kk = lin >> 4, f4 = lin & 15;
                    int j = jbase + c0 + kk;
                    uint4 kv = make_uint4(0,0,0,0), vv = make_uint4(0,0,0,0);
                    if (j >= 0 && j < Lc) {
                        size_t off = (((size_t)b*Lc + j)*Hc + h)*Dc + f4*4;
                        kv = *(const uint4*)(g_lk + off);
                        vv = *(const uint4*)(g_lv + off);
                    }
                    *(uint4*)&sK[kk*68 + f4*4] = kv;
                    *(uint4*)&sV[kk*72 + f4*4] = vv;
                }
            } else {
                const int g0 = (tile - 6) * 64;
                #pragma unroll
                for (int it = 0; it < 4; ++it) {
                    int lin = tid + it * 256;
                    int kk = lin >> 4, f4 = lin & 15;
                    size_t off = (((size_t)b*Gc + g0 + kk)*Hc + h)*Dc + f4*4;
                    *(uint4*)&sK[kk*68 + f4*4] = *(const uint4*)(g_gk + off);
                    *(uint4*)&sV[kk*72 + f4*4] = *(const uint4*)(g_gv + off);
                }
            }
            __syncthreads();

            float sc[8][4];
            #pragma unroll
            for (int nf = 0; nf < 8; ++nf)
                #pragma unroll
                for (int e = 0; e < 4; ++e) sc[nf][e] = 0.f;
            #pragma unroll
            for (int kf = 0; kf < 8; ++kf)
                #pragma unroll
                for (int nf = 0; nf < 8; ++nf) {
                    uint32_t b0 = sK[(nf*8 + g) * 68 + kf*8 + tg];
                    uint32_t b1 = sK[(nf*8 + g) * 68 + kf*8 + tg + 4];
                    mma8(sc[nf], qa[kf], b0, b1);
                }

            #pragma unroll
            for (int nf = 0; nf < 8; ++nf) {
                uint2 pw;
                #pragma unroll
                for (int half = 0; half < 2; ++half) {
                    const int pr = half ? pr1 : pr0;
                    const unsigned char* prL = half ? prow1L : prow0L;
                    const unsigned char* prG = half ? prow1G : prow0G;
                    float ps = 0.f;
                    #pragma unroll
                    for (int sub = 0; sub < 2; ++sub) {
                        const int e = half*2 + sub;
                        const int cl = nf*8 + 2*tg + sub;
                        unsigned char byt; bool ok;
                        if (tile < 6) {
                            int c = tile*64 + cl;
                            int r = c - pr - 1;
                            int j = jbase + c;
                            ok = (r >= 0) && (r < Wc) && (j >= 0) && (j < Lc);
                            byt = ok ? prL[r] : (unsigned char)0;
                        } else {
                            byt = prG[(tile - 6)*64 + cl];
                            ok = true;
                        }
                        ok = ok && (byt & 0x80);
                        float s = (sc[nf][e] + sRel[pr*33 + (byt & 31)]) * SCALEc;
                        float p = ok ? __expf(s) : 0.f;
                        uint32_t pt = to_tf32(p);
                        ps += __uint_as_float(pt);
                        if (sub == 0) pw.x = pt; else pw.y = pt;
                    }
                    if (half == 0) ls0 += ps; else ls1 += ps;
                    *(uint2*)&sQ[pr*68 + nf*8 + 2*tg] = pw;
                }
            }
            __syncwarp();

            #pragma unroll
            for (int kf = 0; kf < 8; ++kf) {
                uint32_t pa[4];
                pa[0] = sQ[pr0*68 + kf*8 + tg];
                pa[1] = sQ[pr1*68 + kf*8 + tg];
                pa[2] = sQ[pr0*68 + kf*8 + tg + 4];
                pa[3] = sQ[pr1*68 + kf*8 + tg + 4];
                #pragma unroll
                for (int nf = 0; nf < 8; ++nf) {
                    uint32_t b0 = sV[(kf*8 + tg) * 72 + nf*8 + g];
                    uint32_t b1 = sV[(kf*8 + tg + 4) * 72 + nf*8 + g];
                    mma8(accO[nf], pa, b0, b1);
                }
            }
            __syncwarp();
        }

        ls0 += __shfl_xor_sync(0xFFFFFFFF, ls0, 1);
        ls0 += __shfl_xor_sync(0xFFFFFFFF, ls0, 2);
        ls1 += __shfl_xor_sync(0xFFFFFFFF, ls1, 1);
        ls1 += __shfl_xor_sync(0xFFFFFFFF, ls1, 2);
        const float inv0 = 1.f / ls0, inv1 = 1.f / ls1;

        #pragma unroll
        for (int nf = 0; nf < 8; ++nf) {
            int c = nf*8 + 2*tg;
            float2 v0 = make_float2(round_tf32(accO[nf][0]*inv0), round_tf32(accO[nf][1]*inv0));
            float2 v1 = make_float2(round_tf32(accO[nf][2]*inv1), round_tf32(accO[nf][3]*inv1));
            *(float2*)(g_lctx + (((size_t)b*Lc + t0 + pr0)*Hc + h)*Dc + c) = v0;
            *(float2*)(g_lctx + (((size_t)b*Lc + t0 + pr1)*Hc + h)*Dc + c) = v1;
        }
    } else {
        // ================= global-token attention (split-K) =================
        const int gid = bid;
        const int qt = gid & 1;
        const int split = (gid >> 1) & (GSPLIT - 1);
        const int bh = gid >> 3;
        const int b = bh / Hc, h = bh % Hc;
        const int q0 = qt * 128;

        #pragma unroll
        for (int it = 0; it < 8; ++it) {
            int lin = tid + it * 256;
            int row = lin >> 4, f4 = lin & 15;
            uint4 v = *(const uint4*)(g_gq + (((size_t)b*Gc + q0 + row)*Hc + h)*Dc + f4*4);
            *(uint4*)&sQ[row * 68 + f4 * 4] = v;
        }
        #pragma unroll
        for (int it = 0; it < 2; ++it) {
            int lin = tid + it * 256;
            int r = lin >> 4, f4 = lin & 15;
            float4 v = *(const float4*)(rel_embG + ((size_t)r*Hc + h)*Dc + f4*4);
            uint4 w;
            w.x = to_tf32(v.x); w.y = to_tf32(v.y); w.z = to_tf32(v.z); w.w = to_tf32(v.w);
            *(uint4*)&sK[r * 68 + f4 * 4] = w;
        }
        __syncthreads();

        uint32_t qa[8][4];
        #pragma unroll
        for (int kf = 0; kf < 8; ++kf) {
            int k0 = kf * 8;
            qa[kf][0] = sQ[pr0 * 68 + k0 + tg];
            qa[kf][1] = sQ[pr1 * 68 + k0 + tg];
            qa[kf][2] = sQ[pr0 * 68 + k0 + tg + 4];
            qa[kf][3] = sQ[pr1 * 68 + k0 + tg + 4];
        }

        {
            float rc[4][4];
            #pragma unroll
            for (int nf = 0; nf < 4; ++nf)
                #pragma unroll
                for (int e = 0; e < 4; ++e) rc[nf][e] = 0.f;
            #pragma unroll
            for (int kf = 0; kf < 8; ++kf)
                #pragma unroll
                for (int nf = 0; nf < 4; ++nf) {
                    uint32_t b0 = sK[(nf*8 + g) * 68 + kf*8 + tg];
                    uint32_t b1 = sK[(nf*8 + g) * 68 + kf*8 + tg + 4];
                    mma8(rc[nf], qa[kf], b0, b1);
                }
            #pragma unroll
            for (int nf = 0; nf < 4; ++nf) {
                int c = nf * 8 + 2 * tg;
                sRel[pr0*33 + c]     = rc[nf][0] + rel_biasG[c*Hc + h];
                sRel[pr0*33 + c + 1] = rc[nf][1] + rel_biasG[(c+1)*Hc + h];
                sRel[pr1*33 + c]     = rc[nf][2] + rel_biasG[c*Hc + h];
                sRel[pr1*33 + c + 1] = rc[nf][3] + rel_biasG[(c+1)*Hc + h];
            }
        }

        float accO[8][4];
        #pragma unroll
        for (int nf = 0; nf < 8; ++nf)
            #pragma unroll
            for (int e = 0; e < 4; ++e) accO[nf][e] = 0.f;
        float ls0 = 0.f, ls1 = 0.f;

        const unsigned char* prow0 = g_pg + (size_t)(b*Gc + q0 + pr0)*KTOTG;
        const unsigned char* prow1 = g_pg + (size_t)(b*Gc + q0 + pr1)*KTOTG;

        #pragma unroll 1
        for (int tt = 0; tt < 17; ++tt) {
            const int tile = split * 17 + tt;
            const int j0 = tile * 64;
            __syncthreads();
            #pragma unroll
            for (int it = 0; it < 4; ++it) {
                int lin = tid + it * 256;
                int kk = lin >> 4, f4 = lin & 15;
                int j = j0 + kk;
                size_t off;
                const float *kp, *vp;
                if (j < Gc) { off = (((size_t)b*Gc + j)*Hc + h)*Dc + f4*4;        kp = g_gk; vp = g_gv; }
                else        { off = (((size_t)b*Lc + (j - Gc))*Hc + h)*Dc + f4*4; kp = g_lk; vp = g_lv; }
                *(uint4*)&sK[kk*68 + f4*4] = *(const uint4*)(kp + off);
                *(uint4*)&sV[kk*72 + f4*4] = *(const uint4*)(vp + off);
            }
            __syncthreads();

            float sc[8][4];
            #pragma unroll
            for (int nf = 0; nf < 8; ++nf)
                #pragma unroll
                for (int e = 0; e < 4; ++e) sc[nf][e] = 0.f;
            #pragma unroll
            for (int kf = 0; kf < 8; ++kf)
                #pragma unroll
                for (int nf = 0; nf < 8; ++nf) {
                    uint32_t b0 = sK[(nf*8 + g) * 68 + kf*8 + tg];
                    uint32_t b1 = sK[(nf*8 + g) * 68 + kf*8 + tg + 4];
                    mma8(sc[nf], qa[kf], b0, b1);
                }

            #pragma unroll
            for (int nf = 0; nf < 8; ++nf) {
                uint2 pw;
                #pragma unroll
                for (int half = 0; half < 2; ++half) {
                    const int pr = half ? pr1 : pr0;
                    const unsigned char* prW = half ? prow1 : prow0;
                    float ps = 0.f;
                    #pragma unroll
                    for (int sub = 0; sub < 2; ++sub) {
                        const int e = half*2 + sub;
                        const int cl = nf*8 + 2*tg + sub;
                        unsigned char byt = prW[j0 + cl];
                        bool ok = (byt & 0x80) != 0;
                        float s = (sc[nf][e] + sRel[pr*33 + (byt & 31)]) * SCALEc;
                        float p = ok ? __expf(s) : 0.f;
                        uint32_t pt = to_tf32(p);
                        ps += __uint_as_float(pt);
                        if (sub == 0) pw.x = pt; else pw.y = pt;
                    }
                    if (half == 0) ls0 += ps; else ls1 += ps;
                    *(uint2*)&sQ[pr*68 + nf*8 + 2*tg] = pw;
                }
            }
            __syncwarp();

            #pragma unroll
            for (int kf = 0; kf < 8; ++kf) {
                uint32_t pa[4];
                pa[0] = sQ[pr0*68 + kf*8 + tg];
                pa[1] = sQ[pr1*68 + kf*8 + tg];
                pa[2] = sQ[pr0*68 + kf*8 + tg + 4];
                pa[3] = sQ[pr1*68 + kf*8 + tg + 4];
                #pragma unroll
                for (int nf = 0; nf < 8; ++nf) {
                    uint32_t b0 = sV[(kf*8 + tg) * 72 + nf*8 + g];
                    uint32_t b1 = sV[(kf*8 + tg + 4) * 72 + nf*8 + g];
                    mma8(accO[nf], pa, b0, b1);
                }
            }
            __syncwarp();
        }

        ls0 += __shfl_xor_sync(0xFFFFFFFF, ls0, 1);
        ls0 += __shfl_xor_sync(0xFFFFFFFF, ls0, 2);
        ls1 += __shfl_xor_sync(0xFFFFFFFF, ls1, 1);
        ls1 += __shfl_xor_sync(0xFFFFFFFF, ls1, 2);

        const int pi = (bh * 2 + qt) * GSPLIT + split;
        float* pa = g_part_acc + (size_t)pi * 128 * 64;
        #pragma unroll
        for (int nf = 0; nf < 8; ++nf) {
            int c = nf*8 + 2*tg;
            *(float2*)(pa + pr0*64 + c) = make_float2(accO[nf][0], accO[nf][1]);
            *(float2*)(pa + pr1*64 + c) = make_float2(accO[nf][2], accO[nf][3]);
        }
        if (tg == 0) {
            g_part_l[pi*128 + pr0] = ls0;
            g_part_l[pi*128 + pr1] = ls1;
        }
    }
}

__global__ void glob_combine2() {
    const int bq = blockIdx.x >> 7;
    const int row = blockIdx.x & 127;
    const int d = threadIdx.x;
    const int bh = bq >> 1, qt = bq & 1;
    const int b = bh / Hc, h = bh % Hc;
    const int qi = qt * 128 + row;
    float a = 0.f, l = 0.f;
    #pragma unroll
    for (int s = 0; s < GSPLIT; ++s) {
        int pi = bq * GSPLIT + s;
        a += g_part_acc[(size_t)pi*128*64 + row*64 + d];
        l += g_part_l[pi*128 + row];
    }
    g_gctx[(((size_t)b*Gc + qi)*Hc + h)*Dc + d] = round_tf32(a / l);
}

// ---------------- host launcher ----------------
extern "C" void kernel_launch(void* const* d_in, const int* in_sizes, int n_in,
                              void* d_out, int out_size) {
    (void)in_sizes; (void)n_in; (void)out_size;

    const float* long_input   = (const float*)d_in[0];
    const float* global_input = (const float*)d_in[1];
    const int* l2l_m = (const int*)d_in[2];
    const int* g2g_m = (const int*)d_in[3];
    const int* l2g_m = (const int*)d_in[4];
    const int* g2l_m = (const int*)d_in[5];
    const int* l2l_i = (const int*)d_in[6];
    const int* g2g_i = (const int*)d_in[7];
    const int* l2g_i = (const int*)d_in[8];
    const int* g2l_i = (const int*)d_in[9];
    const float* wq_long = (const float*)d_in[10];
    const float* bq_long = (const float*)d_in[11];
    const float* wk_long = (const float*)d_in[12];
    const float* bk_long = (const float*)d_in[13];
    const float* wv_long = (const float*)d_in[14];
    const float* bv_long = (const float*)d_in[15];
    const float* wq_glob = (const float*)d_in[16];
    const float* bq_glob = (const float*)d_in[17];
    const float* wk_glob = (const float*)d_in[18];
    const float* bk_glob = (const float*)d_in[19];
    const float* wv_glob = (const float*)d_in[20];
    const float* bv_glob = (const float*)d_in[21];
    const float* rel_emb_long  = (const float*)d_in[22];
    const float* rel_bias_long = (const float*)d_in[23];
    const float* rel_emb_glob  = (const float*)d_in[24];
    const float* rel_bias_glob = (const float*)d_in[25];
    const float* wo_long = (const float*)d_in[26];
    const float* bo_long = (const float*)d_in[27];
    const float* wo_glob = (const float*)d_in[28];
    const float* bo_glob = (const float*)d_in[29];

    cudaFuncSetAttribute(gemm_mma_qkv, cudaFuncAttributeMaxDynamicSharedMemorySize, GEMM_SMEM);
    cudaFuncSetAttribute(gemm_mma_out, cudaFuncAttributeMaxDynamicSharedMemorySize, GEMM_SMEM);
    cudaFuncSetAttribute(attn_mma, cudaFuncAttributeMaxDynamicSharedMemorySize, ATT_SMEM);

    // 0) pre-convert inputs/weights
    {
        int n4 = N4A + N4G + 8*N4W;
        cvt_all_kernel<<<(n4 + 255)/256, 256>>>(long_input, global_input,
                                                wq_long, wk_long, wv_long, wo_long,
                                                wq_glob, wk_glob, wv_glob, wo_glob);
    }

    // 1) pack mask+id bytes
    {
        int ntot = NPL + NPG2 + NPGL;
        pack_all_kernel<<<(ntot + 255)/256, 256>>>(l2l_m, l2l_i, l2g_m, l2g_i,
                                                   g2g_m, g2g_i, g2l_m, g2l_i);
    }

    // 2) all QKV projections in one launch
    dim3 gqkv(HIDc/128, 68, 3);
    gemm_mma_qkv<<<gqkv, 256, GEMM_SMEM>>>(bq_long, bk_long, bv_long,
                                           bq_glob, bk_glob, bv_glob);

    // 3) fused attention (glob CTAs first)
    attn_mma<<<NLONG + NGLOB, 256, ATT_SMEM>>>(rel_emb_long, rel_bias_long,
                                               rel_emb_glob, rel_bias_glob);
    glob_combine2<<<Bc*Hc*2*128, 64>>>();

    // 4) both output projections in one launch
    float* out_long = (float*)d_out;
    float* out_glob = out_long + (size_t)Bc*Lc*HIDc;
    dim3 gout(HIDc/128, 68);
    gemm_mma_out<<<gout, 256, GEMM_SMEM>>>(bo_long, bo_glob, out_long, out_glob);
}